// round 3
// baseline (speedup 1.0000x reference)
#include <cuda_runtime.h>

// ---------------------------------------------------------------------------
// fp4 (bitsandbytes) dequant + GEMV:  y[4, M] = x[4, N] @ W[M, N]^T + bias
//   qweight: numel/2 int32, each holding ONE byte (two 4-bit codebook indices)
//   absmax : per-64-element block scale
//   code   : 16-entry fp4 codebook
// Layout: 128-thread blocks (4 warps), 4 rows per warp, each lane owns an
// int2 (= 2 qweight int32s = 2 bytes = 4 consecutive n) per iteration.
// ---------------------------------------------------------------------------

static __device__ __forceinline__ unsigned long long pk2(float lo, float hi) {
    unsigned long long r;
    asm("mov.b64 %0, {%1, %2};" : "=l"(r) : "f"(lo), "f"(hi));
    return r;
}
static __device__ __forceinline__ void up2(unsigned long long v, float& lo, float& hi) {
    asm("mov.b64 {%0, %1}, %2;" : "=f"(lo), "=f"(hi) : "l"(v));
}
static __device__ __forceinline__ unsigned long long f2fma(unsigned long long a,
                                                           unsigned long long b,
                                                           unsigned long long c) {
    unsigned long long d;
    asm("fma.rn.f32x2 %0, %1, %2, %3;" : "=l"(d) : "l"(a), "l"(b), "l"(c));
    return d;
}
static __device__ __forceinline__ unsigned long long f2add(unsigned long long a,
                                                           unsigned long long b) {
    unsigned long long d;
    asm("add.rn.f32x2 %0, %1, %2;" : "=l"(d) : "l"(a), "l"(b));
    return d;
}

constexpr int MD  = 8192;      // out features
constexpr int ND  = 8192;      // in features
constexpr int RW  = 4;         // rows per warp
constexpr int WPB = 4;         // warps per block (128 threads)
constexpr int RPB = RW * WPB;  // 16 rows per block

__global__ void __launch_bounds__(128, 8)
fp4_gemv(const float* __restrict__ x, const int* __restrict__ qw,
         const float* __restrict__ am, const float* __restrict__ code,
         const float* __restrict__ bias, float* __restrict__ out)
{
    const int lane = threadIdx.x & 31;
    const int wid  = threadIdx.x >> 5;

    // Register-resident codebook: lane l holds code[l & 15]; decode = shfl by nibble.
    const float creg = code[lane & 15];

    const int row0 = blockIdx.x * RPB + wid * RW;

    unsigned long long a01[RW], a23[RW];
#pragma unroll
    for (int r = 0; r < RW; r++) { a01[r] = 0ull; a23[r] = 0ull; }

    const int2* q2 = reinterpret_cast<const int2*>(qw);
    const int ldq = ND / 4;    // int2 per row (2048)
    const int lda = ND / 64;   // absmax blocks per row (128)

    // Each lane owns int2 index li within each of its 4 rows.
    // One int2 = 2 int32 = 2 packed bytes = 4 weights = n in [4*li, 4*li+4).
#pragma unroll 2
    for (int it = 0; it < (ND / 4) / 32; ++it) {
        const int li = it * 32 + lane;
        const int nb = li * 4;

        // x window: 4 consecutive n for all 4 batches, packed as (b0,b1) / (b2,b3).
        unsigned long long x01[4], x23[4];
        {
            const float4 v0 = *reinterpret_cast<const float4*>(x + 0 * ND + nb);
            const float4 v1 = *reinterpret_cast<const float4*>(x + 1 * ND + nb);
            const float4 v2 = *reinterpret_cast<const float4*>(x + 2 * ND + nb);
            const float4 v3 = *reinterpret_cast<const float4*>(x + 3 * ND + nb);
            x01[0] = pk2(v0.x, v1.x); x01[1] = pk2(v0.y, v1.y);
            x01[2] = pk2(v0.z, v1.z); x01[3] = pk2(v0.w, v1.w);
            x23[0] = pk2(v2.x, v3.x); x23[1] = pk2(v2.y, v3.y);
            x23[2] = pk2(v2.z, v3.z); x23[3] = pk2(v2.w, v3.w);
        }

#pragma unroll
        for (int r = 0; r < RW; r++) {
            const int row = row0 + r;
            const int2 q  = __ldg(&q2[row * ldq + li]);
            // absmax block (64 n) covers the whole 4-n window: block = li/16
            const float s = __ldg(&am[row * lda + (li >> 4)]);
#pragma unroll
            for (int j = 0; j < 2; j++) {
                const int b = (j == 0) ? q.x : q.y;   // one byte, already 0..255
                const float chi = __shfl_sync(0xffffffffu, creg, b >> 4);   // n = 2j
                const float clo = __shfl_sync(0xffffffffu, creg, b & 15);   // n = 2j+1
                const float w0 = chi * s;
                const float w1 = clo * s;
                const unsigned long long s0 = pk2(w0, w0);
                const unsigned long long s1 = pk2(w1, w1);
                a01[r] = f2fma(s0, x01[2 * j],     a01[r]);
                a01[r] = f2fma(s1, x01[2 * j + 1], a01[r]);
                a23[r] = f2fma(s0, x23[2 * j],     a23[r]);
                a23[r] = f2fma(s1, x23[2 * j + 1], a23[r]);
            }
        }
    }

    // Butterfly reduction over lanes (packed f32x2 adds).
#pragma unroll
    for (int r = 0; r < RW; r++) {
#pragma unroll
        for (int off = 16; off > 0; off >>= 1) {
            a01[r] = f2add(a01[r], __shfl_xor_sync(0xffffffffu, a01[r], off));
            a23[r] = f2add(a23[r], __shfl_xor_sync(0xffffffffu, a23[r], off));
        }
    }

#pragma unroll
    for (int r = 0; r < RW; r++) {
        if (lane == r) {
            const int row = row0 + r;
            float y0, y1, y2, y3;
            up2(a01[r], y0, y1);
            up2(a23[r], y2, y3);
            const float bb = bias[row];
            out[0 * MD + row] = y0 + bb;
            out[1 * MD + row] = y1 + bb;
            out[2 * MD + row] = y2 + bb;
            out[3 * MD + row] = y3 + bb;
        }
    }
}

extern "C" void kernel_launch(void* const* d_in, const int* in_sizes, int n_in,
                              void* d_out, int out_size)
{
    const float* x    = (const float*)d_in[0];
    const int*   qw   = (const int*)d_in[1];
    const float* am   = (const float*)d_in[2];
    const float* code = (const float*)d_in[3];
    const float* bias = (const float*)d_in[4];
    float*       out  = (float*)d_out;

    fp4_gemv<<<MD / RPB, 128>>>(x, qw, am, code, bias, out);
}

// round 4
// speedup vs baseline: 1.1821x; 1.1821x over previous
#include <cuda_runtime.h>
#include <cstdint>

// ---------------------------------------------------------------------------
// fp4 (bitsandbytes) dequant + GEMV:  y[4, M] = x[4, N] @ W[M, N]^T + bias
// qweight: numel/2 int32, each holding ONE byte (two 4-bit nibbles, hi first)
// absmax : per-64-element block scale; code: 16-entry codebook.
//
// Stage 1 (fp4_main): grid = (16 N-slices, 256 row-groups), 256 threads.
//   Per block: bulk-async (TMA-pipe) copy of the 32KB qweight tile + 1KB
//   absmax tile into smem; x slice staged batch-interleaved + SW128-swizzled.
//   Decode via register-shfl codebook, packed f32x2 FMAs, per-iter absmax
//   folding. Warp butterfly -> partial sums to a device buffer.
// Stage 2 (fp4_reduce): sum 16 partials + bias -> out. Deterministic.
// ---------------------------------------------------------------------------

constexpr int MD = 8192, ND = 8192;
constexpr int SPLIT = 16;
constexpr int SLICE = ND / SPLIT;        // 512 n per slice
constexpr int RPB = 32;                  // rows per block (8 warps x 4 rows)
constexpr int QI_ROW = SLICE / 2;        // int32 per row-slice = 256 (1KB)
constexpr int AM_ROW = SLICE / 64;       // absmax per row-slice = 8
constexpr int ITERS = SLICE / (32 * 8);  // 2 iterations (8 n per lane per iter)

__device__ float g_part[4 * MD * SPLIT];  // [(b*MD + row)*SPLIT + split]

static __device__ __forceinline__ unsigned long long pk2(float lo, float hi) {
    unsigned long long r;
    asm("mov.b64 %0, {%1, %2};" : "=l"(r) : "f"(lo), "f"(hi));
    return r;
}
static __device__ __forceinline__ void up2(unsigned long long v, float& lo, float& hi) {
    asm("mov.b64 {%0, %1}, %2;" : "=f"(lo), "=f"(hi) : "l"(v));
}
static __device__ __forceinline__ unsigned long long f2fma(unsigned long long a,
                                                           unsigned long long b,
                                                           unsigned long long c) {
    unsigned long long d;
    asm("fma.rn.f32x2 %0, %1, %2, %3;" : "=l"(d) : "l"(a), "l"(b), "l"(c));
    return d;
}
static __device__ __forceinline__ unsigned long long f2mul(unsigned long long a,
                                                           unsigned long long b) {
    unsigned long long d;
    asm("mul.rn.f32x2 %0, %1, %2;" : "=l"(d) : "l"(a), "l"(b));
    return d;
}
static __device__ __forceinline__ unsigned long long f2add(unsigned long long a,
                                                           unsigned long long b) {
    unsigned long long d;
    asm("add.rn.f32x2 %0, %1, %2;" : "=l"(d) : "l"(a), "l"(b));
    return d;
}
static __device__ __forceinline__ uint32_t s2u(const void* p) {
    uint32_t a;
    asm("{.reg .u64 t; cvta.to.shared.u64 t, %1; cvt.u32.u64 %0, t;}" : "=r"(a) : "l"(p));
    return a;
}
static __device__ __forceinline__ void bulk_cp(uint32_t dst, const void* src,
                                               uint32_t bytes, uint32_t mbar) {
    asm volatile(
        "cp.async.bulk.shared::cluster.global.mbarrier::complete_tx::bytes "
        "[%0], [%1], %2, [%3];"
        :: "r"(dst), "l"(src), "r"(bytes), "r"(mbar) : "memory");
}
#define SW128(o) ((o) ^ (((o) >> 3) & 0x70))

__global__ void __launch_bounds__(256, 3)
fp4_main(const float* __restrict__ x, const int* __restrict__ qw,
         const float* __restrict__ am, const float* __restrict__ code)
{
    __shared__ uint4 q_sm[RPB * QI_ROW / 4];               // 32 KB
    __shared__ float4 x_sm[SLICE];                          // 8 KB (swizzled)
    __shared__ float  am_sm[RPB * AM_ROW];                  // 1 KB
    __shared__ __align__(8) unsigned long long mbar;

    const int tid  = threadIdx.x;
    const int lane = tid & 31;
    const int wid  = tid >> 5;
    const int split   = blockIdx.x;
    const int rowbase = blockIdx.y * RPB;

    const uint32_t mb = s2u(&mbar);
    const uint32_t qb = s2u(q_sm);
    const uint32_t ab = s2u(am_sm);
    const char* xsm   = reinterpret_cast<const char*>(x_sm);

    if (tid == 0) {
        asm volatile("mbarrier.init.shared.b64 [%0], 1;" :: "r"(mb) : "memory");
    }
    __syncthreads();

    if (tid == 0) {
        asm volatile("mbarrier.arrive.expect_tx.shared.b64 _, [%0], %1;"
                     :: "r"(mb), "r"((uint32_t)(RPB * 1024 + RPB * 32)) : "memory");
    }
    if (tid < RPB) {
        const int row = rowbase + tid;
        bulk_cp(qb + tid * 1024, qw + row * (ND / 2) + split * QI_ROW, 1024, mb);
        bulk_cp(ab + tid * 32,   am + row * (ND / 64) + split * AM_ROW, 32, mb);
    }

    // Stage x slice batch-interleaved: x_sm[n] = (b0,b1,b2,b3), SW128-swizzled.
    {
        const int n0 = split * SLICE;
#pragma unroll
        for (int k = 0; k < SLICE / 256; k++) {
            const int idx = k * 256 + tid;
            float4 v;
            v.x = x[0 * ND + n0 + idx];
            v.y = x[1 * ND + n0 + idx];
            v.z = x[2 * ND + n0 + idx];
            v.w = x[3 * ND + n0 + idx];
            *reinterpret_cast<float4*>(const_cast<char*>(xsm) + SW128(idx * 16)) = v;
        }
    }
    __syncthreads();   // x ready

    // Wait for q/am tiles (acquire).
    {
        uint32_t done;
        asm volatile(
            "{\n\t.reg .pred p;\n\t"
            "mbarrier.try_wait.parity.acquire.cta.shared::cta.b64 p, [%1], 0;\n\t"
            "selp.b32 %0, 1, 0, p;\n\t}"
            : "=r"(done) : "r"(mb) : "memory");
        if (!done) {
            asm volatile(
                "{\n\t.reg .pred P1;\n\t"
                "W0_%=:\n\t"
                "mbarrier.try_wait.parity.acquire.cta.shared::cta.b64 P1, [%0], 0, 0x989680;\n\t"
                "@P1 bra.uni WD_%=;\n\t"
                "bra.uni W0_%=;\n\t"
                "WD_%=:\n\t}"
                :: "r"(mb) : "memory");
        }
    }

    // Register-resident codebook: lane l holds code[l & 15].
    const float creg = code[lane & 15];

    unsigned long long a01[4] = {0, 0, 0, 0}, a23[4] = {0, 0, 0, 0};

#pragma unroll
    for (int it = 0; it < ITERS; ++it) {
        const int li = it * 32 + lane;     // uint4 index within a row (0..63)

        // x window: 8 n, each as (b0,b1)|(b2,b3) u64 pair. Conflict-free LDS.128.
        ulonglong2 w[8];
#pragma unroll
        for (int j = 0; j < 8; j++) {
            w[j] = *reinterpret_cast<const ulonglong2*>(xsm + SW128((li * 8 + j) * 16));
        }

#pragma unroll
        for (int r = 0; r < 4; r++) {
            const int rl = wid * 4 + r;
            const uint4 q = q_sm[rl * (QI_ROW / 4) + li];
            const float s = am_sm[rl * AM_ROW + (li >> 3)];

            unsigned long long t01, t23;
            const int bq[4] = { (int)q.x, (int)q.y, (int)q.z, (int)q.w };
#pragma unroll
            for (int jj = 0; jj < 4; jj++) {
                const int b = bq[jj];
                const float chi = __shfl_sync(0xffffffffu, creg, b >> 4);
                const float clo = __shfl_sync(0xffffffffu, creg, b & 15);
                const unsigned long long c0 = pk2(chi, chi);
                const unsigned long long c1 = pk2(clo, clo);
                if (jj == 0) {
                    t01 = f2mul(c0, w[0].x);
                    t23 = f2mul(c0, w[0].y);
                } else {
                    t01 = f2fma(c0, w[2 * jj].x, t01);
                    t23 = f2fma(c0, w[2 * jj].y, t23);
                }
                t01 = f2fma(c1, w[2 * jj + 1].x, t01);
                t23 = f2fma(c1, w[2 * jj + 1].y, t23);
            }
            const unsigned long long ss = pk2(s, s);
            a01[r] = f2fma(t01, ss, a01[r]);
            a23[r] = f2fma(t23, ss, a23[r]);
        }
    }

    // Butterfly reduction (packed f32x2 adds).
#pragma unroll
    for (int r = 0; r < 4; r++) {
#pragma unroll
        for (int off = 16; off > 0; off >>= 1) {
            a01[r] = f2add(a01[r], __shfl_xor_sync(0xffffffffu, a01[r], off));
            a23[r] = f2add(a23[r], __shfl_xor_sync(0xffffffffu, a23[r], off));
        }
    }

#pragma unroll
    for (int r = 0; r < 4; r++) {
        if (lane == r) {
            const int row = rowbase + wid * 4 + r;
            float y0, y1, y2, y3;
            up2(a01[r], y0, y1);
            up2(a23[r], y2, y3);
            g_part[(0 * MD + row) * SPLIT + split] = y0;
            g_part[(1 * MD + row) * SPLIT + split] = y1;
            g_part[(2 * MD + row) * SPLIT + split] = y2;
            g_part[(3 * MD + row) * SPLIT + split] = y3;
        }
    }
}

__global__ void __launch_bounds__(256)
fp4_reduce(const float* __restrict__ bias, float* __restrict__ out)
{
    const int i = blockIdx.x * 256 + threadIdx.x;   // i = b*MD + row
    if (i >= 4 * MD) return;
    const int row = i & (MD - 1);
    const float4* p = reinterpret_cast<const float4*>(g_part + i * SPLIT);
    float4 s0 = p[0], s1 = p[1], s2 = p[2], s3 = p[3];
    float acc = ((s0.x + s0.y) + (s0.z + s0.w))
              + ((s1.x + s1.y) + (s1.z + s1.w))
              + ((s2.x + s2.y) + (s2.z + s2.w))
              + ((s3.x + s3.y) + (s3.z + s3.w));
    out[i] = acc + bias[row];
}

extern "C" void kernel_launch(void* const* d_in, const int* in_sizes, int n_in,
                              void* d_out, int out_size)
{
    const float* x    = (const float*)d_in[0];
    const int*   qw   = (const int*)d_in[1];
    const float* am   = (const float*)d_in[2];
    const float* code = (const float*)d_in[3];
    const float* bias = (const float*)d_in[4];
    float*       out  = (float*)d_out;

    dim3 grid(SPLIT, MD / RPB);
    fp4_main<<<grid, 256>>>(x, qw, am, code);
    fp4_reduce<<<(4 * MD) / 256, 256>>>(bias, out);
}

// round 5
// speedup vs baseline: 1.5063x; 1.2743x over previous
#include <cuda_runtime.h>
#include <cstdint>

// ---------------------------------------------------------------------------
// fp4 (bitsandbytes) dequant + GEMV:  y[4, M] = x[4, N] @ W[M, N]^T + bias
//   qweight: numel/2 int32, each holding ONE byte (two nibbles, hi first)
//   absmax : per-64-element block scale; code: 16-entry codebook
//
// Transposed lane mapping: a warp owns a contiguous 64-n "step"; lane l takes
// the packed byte at int32 index (step*32 + l), i.e. n = 2l, 2l+1. This makes
// every x load LDG.64 lane-consecutive (2 L1 wavefronts instead of 8) and the
// absmax scale warp-uniform per step. 4 rows per warp, 4 warps per block,
// N split in 2 halves; a tiny deterministic reduce sums the partials + bias.
// ---------------------------------------------------------------------------

constexpr int MD = 8192, ND = 8192;
constexpr int NSPLIT = 2;
constexpr int NHALF  = ND / NSPLIT;     // 4096 n per block
constexpr int STEPS  = NHALF / 64;      // 64 steps (one absmax block each)
constexpr int RW = 4;                   // rows per warp
constexpr int WPB = 4;                  // warps per block (128 threads)
constexpr int RPB = RW * WPB;           // 16 rows per block

__device__ float g_part[NSPLIT * 4 * MD];   // [split][batch][row]

static __device__ __forceinline__ unsigned long long pk2(float lo, float hi) {
    unsigned long long r;
    asm("mov.b64 %0, {%1, %2};" : "=l"(r) : "f"(lo), "f"(hi));
    return r;
}
static __device__ __forceinline__ void up2(unsigned long long v, float& lo, float& hi) {
    asm("mov.b64 {%0, %1}, %2;" : "=f"(lo), "=f"(hi) : "l"(v));
}
static __device__ __forceinline__ unsigned long long f2fma(unsigned long long a,
                                                           unsigned long long b,
                                                           unsigned long long c) {
    unsigned long long d;
    asm("fma.rn.f32x2 %0, %1, %2, %3;" : "=l"(d) : "l"(a), "l"(b), "l"(c));
    return d;
}
static __device__ __forceinline__ unsigned long long f2add(unsigned long long a,
                                                           unsigned long long b) {
    unsigned long long d;
    asm("add.rn.f32x2 %0, %1, %2;" : "=l"(d) : "l"(a), "l"(b));
    return d;
}

__global__ void __launch_bounds__(128, 8)
fp4_main(const float* __restrict__ x, const int* __restrict__ qw,
         const float* __restrict__ am, const float* __restrict__ code)
{
    const int lane = threadIdx.x & 31;
    const int wid  = threadIdx.x >> 5;
    const int split = blockIdx.x;              // 0 or 1
    const int row0  = blockIdx.y * RPB + wid * RW;
    const int n0    = split * NHALF;

    // Register-resident codebook: lane l holds code[l & 15]; decode via shfl.
    const float creg = code[lane & 15];

    // Per-row streams for this N-half.
    const int*   q0  = qw + row0 * (ND / 2)  + split * (NHALF / 2);
    const float* am0 = am + row0 * (ND / 64) + split * (NHALF / 64);
    const float2* x0 = reinterpret_cast<const float2*>(x + 0 * ND + n0);
    const float2* x1 = reinterpret_cast<const float2*>(x + 1 * ND + n0);
    const float2* x2 = reinterpret_cast<const float2*>(x + 2 * ND + n0);
    const float2* x3 = reinterpret_cast<const float2*>(x + 3 * ND + n0);

    unsigned long long a01[RW] = {0, 0, 0, 0};
    unsigned long long a23[RW] = {0, 0, 0, 0};

#pragma unroll 4
    for (int step = 0; step < STEPS; ++step) {
        const int col = step * 32 + lane;      // int32 index in the half-row

        // x for this lane's two n (2*col, 2*col+1), all 4 batches. LDG.64,
        // lanes consecutive -> 2 wavefronts each.
        const float2 v0 = __ldg(&x0[col]);
        const float2 v1 = __ldg(&x1[col]);
        const float2 v2 = __ldg(&x2[col]);
        const float2 v3 = __ldg(&x3[col]);
        const unsigned long long xe01 = pk2(v0.x, v1.x);   // n even, batches 0,1
        const unsigned long long xo01 = pk2(v0.y, v1.y);   // n odd
        const unsigned long long xe23 = pk2(v2.x, v3.x);
        const unsigned long long xo23 = pk2(v2.y, v3.y);

#pragma unroll
        for (int r = 0; r < RW; r++) {
            const int   b = __ldg(q0 + r * (ND / 2) + col);        // one byte
            const float s = __ldg(am0 + r * (ND / 64) + step);     // warp-uniform
            const float chi = __shfl_sync(0xffffffffu, creg, b >> 4);   // n = 2l
            const float clo = __shfl_sync(0xffffffffu, creg, b & 15);   // n = 2l+1
            const float w0 = chi * s;
            const float w1 = clo * s;
            const unsigned long long s0 = pk2(w0, w0);
            const unsigned long long s1 = pk2(w1, w1);
            a01[r] = f2fma(s0, xe01, a01[r]);
            a01[r] = f2fma(s1, xo01, a01[r]);
            a23[r] = f2fma(s0, xe23, a23[r]);
            a23[r] = f2fma(s1, xo23, a23[r]);
        }
    }

    // Butterfly reduction over lanes (packed f32x2 adds).
#pragma unroll
    for (int r = 0; r < RW; r++) {
#pragma unroll
        for (int off = 16; off > 0; off >>= 1) {
            a01[r] = f2add(a01[r], __shfl_xor_sync(0xffffffffu, a01[r], off));
            a23[r] = f2add(a23[r], __shfl_xor_sync(0xffffffffu, a23[r], off));
        }
    }

#pragma unroll
    for (int r = 0; r < RW; r++) {
        if (lane == r) {
            const int row = row0 + r;
            float y0, y1, y2, y3;
            up2(a01[r], y0, y1);
            up2(a23[r], y2, y3);
            g_part[(split * 4 + 0) * MD + row] = y0;
            g_part[(split * 4 + 1) * MD + row] = y1;
            g_part[(split * 4 + 2) * MD + row] = y2;
            g_part[(split * 4 + 3) * MD + row] = y3;
        }
    }
}

__global__ void __launch_bounds__(256)
fp4_reduce(const float* __restrict__ bias, float* __restrict__ out)
{
    // i4 indexes groups of 4 consecutive outputs (same batch, consecutive rows).
    const int i4 = blockIdx.x * 256 + threadIdx.x;
    if (i4 >= (4 * MD) / 4) return;
    const int i   = i4 * 4;
    const int row = i & (MD - 1);
    const float4 p0 = *reinterpret_cast<const float4*>(g_part + 0 * 4 * MD + i);
    const float4 p1 = *reinterpret_cast<const float4*>(g_part + 1 * 4 * MD + i);
    const float4 bb = *reinterpret_cast<const float4*>(bias + row);
    float4 o;
    o.x = p0.x + p1.x + bb.x;
    o.y = p0.y + p1.y + bb.y;
    o.z = p0.z + p1.z + bb.z;
    o.w = p0.w + p1.w + bb.w;
    *reinterpret_cast<float4*>(out + i) = o;
}

extern "C" void kernel_launch(void* const* d_in, const int* in_sizes, int n_in,
                              void* d_out, int out_size)
{
    const float* x    = (const float*)d_in[0];
    const int*   qw   = (const int*)d_in[1];
    const float* am   = (const float*)d_in[2];
    const float* code = (const float*)d_in[3];
    const float* bias = (const float*)d_in[4];
    float*       out  = (float*)d_out;

    dim3 grid(NSPLIT, MD / RPB);              // (2, 512) = 1024 blocks
    fp4_main<<<grid, WPB * 32>>>(x, qw, am, code);
    fp4_reduce<<<((4 * MD) / 4 + 255) / 256, 256>>>(bias, out);
}